// round 1
// baseline (speedup 1.0000x reference)
#include <cuda_runtime.h>
#include <math.h>

// ---------------------------------------------------------------------------
// GroupedExperts: per-expert  out = swiglu(x @ W1 + b1) @ W2 + b2
// E=8, T=2048, D=2048, F=2*D=4096.
// R1 baseline: double-buffered 128x128x16 fp32 SGEMM, 8x8 per thread,
// SwiGLU fused into GEMM1 epilogue. Intermediate activation lives in a
// __device__ global scratch array (allocation rules).
// ---------------------------------------------------------------------------

namespace {
constexpr int E_ = 8;
constexpr int T_ = 2048;
constexpr int D_ = 2048;
constexpr int F_ = 4096;   // 2*D

constexpr int BM = 128, BN = 128, BK = 16;
constexpr float ALPHA_ = 1.702f;
constexpr float LIMIT_ = 7.0f;
}

// 8 * 2048 * 2048 floats = 128 MiB scratch for the post-SwiGLU activation.
__device__ float g_act[(size_t)E_ * T_ * D_];

template <bool FUSE_SWIGLU>
__global__ __launch_bounds__(256, 2)
void sgemm_kernel(const float* __restrict__ Ag,
                  const float* __restrict__ Bg,
                  const float* __restrict__ biasg,
                  float* __restrict__ Cg,
                  int M, int N, int K)
{
    const int e = blockIdx.z;
    const float* A    = Ag    + (size_t)e * M * K;
    const float* B    = Bg    + (size_t)e * K * N;
    const float* bias = biasg + (size_t)e * N;
    const int    Cw   = FUSE_SWIGLU ? (N >> 1) : N;   // output row width
    float*       C    = Cg    + (size_t)e * M * Cw;

    __shared__ float As[2][BK][BM];   // transposed A tile: As[k][m]
    __shared__ float Bs[2][BK][BN];   // Bs[k][n]

    const int tid = threadIdx.x;      // 256 threads
    const int tx  = tid & 15;         // column group
    const int ty  = tid >> 4;         // row group

    const int bm = blockIdx.y * BM;
    const int bn = blockIdx.x * BN;

    // ---- global-load index plan ----
    // A tile (128 rows x 16 k): each thread loads 2 float4 of one row.
    const int aRow = tid >> 1;            // 0..127
    const int aK   = (tid & 1) * 8;       // 0 or 8
    // B tile (16 k x 128 cols): each thread loads 2 float4, coalesced.

    float4 pa[2], pb[2];

    const float* Abase = A + (size_t)(bm + aRow) * K + aK;

    // prologue: tile 0
    {
        pa[0] = *(const float4*)(Abase + 0);
        pa[1] = *(const float4*)(Abase + 4);
        #pragma unroll
        for (int l = 0; l < 2; l++) {
            int idx = tid + l * 256;
            int kr  = idx >> 5, nv = idx & 31;
            pb[l] = *(const float4*)(B + (size_t)kr * N + bn + nv * 4);
        }
        #pragma unroll
        for (int v = 0; v < 2; v++) {
            As[0][aK + v * 4 + 0][aRow] = (v ? pa[1].x : pa[0].x);
            As[0][aK + v * 4 + 1][aRow] = (v ? pa[1].y : pa[0].y);
            As[0][aK + v * 4 + 2][aRow] = (v ? pa[1].z : pa[0].z);
            As[0][aK + v * 4 + 3][aRow] = (v ? pa[1].w : pa[0].w);
        }
        #pragma unroll
        for (int l = 0; l < 2; l++) {
            int idx = tid + l * 256;
            int kr  = idx >> 5, nv = idx & 31;
            *(float4*)&Bs[0][kr][nv * 4] = pb[l];
        }
    }
    __syncthreads();

    float acc[8][8];
    #pragma unroll
    for (int i = 0; i < 8; i++)
        #pragma unroll
        for (int j = 0; j < 8; j++) acc[i][j] = 0.0f;

    const int NT = K / BK;

    for (int kt = 0; kt < NT; kt++) {
        const int buf = kt & 1;

        // prefetch next tile (global -> regs)
        if (kt + 1 < NT) {
            const int k0 = (kt + 1) * BK;
            pa[0] = *(const float4*)(Abase + k0 + 0);
            pa[1] = *(const float4*)(Abase + k0 + 4);
            #pragma unroll
            for (int l = 0; l < 2; l++) {
                int idx = tid + l * 256;
                int kr  = idx >> 5, nv = idx & 31;
                pb[l] = *(const float4*)(B + (size_t)(k0 + kr) * N + bn + nv * 4);
            }
        }

        // compute on current buffer
        #pragma unroll
        for (int kk = 0; kk < BK; kk++) {
            float4 a0 = *(const float4*)&As[buf][kk][ty * 8];
            float4 a1 = *(const float4*)&As[buf][kk][ty * 8 + 4];
            float4 b0 = *(const float4*)&Bs[buf][kk][tx * 8];
            float4 b1 = *(const float4*)&Bs[buf][kk][tx * 8 + 4];
            float av[8] = {a0.x, a0.y, a0.z, a0.w, a1.x, a1.y, a1.z, a1.w};
            float bv[8] = {b0.x, b0.y, b0.z, b0.w, b1.x, b1.y, b1.z, b1.w};
            #pragma unroll
            for (int i = 0; i < 8; i++)
                #pragma unroll
                for (int j = 0; j < 8; j++)
                    acc[i][j] = fmaf(av[i], bv[j], acc[i][j]);
        }

        // store prefetched tile into the other buffer
        if (kt + 1 < NT) {
            const int nbuf = buf ^ 1;
            #pragma unroll
            for (int v = 0; v < 2; v++) {
                As[nbuf][aK + v * 4 + 0][aRow] = (v ? pa[1].x : pa[0].x);
                As[nbuf][aK + v * 4 + 1][aRow] = (v ? pa[1].y : pa[0].y);
                As[nbuf][aK + v * 4 + 2][aRow] = (v ? pa[1].z : pa[0].z);
                As[nbuf][aK + v * 4 + 3][aRow] = (v ? pa[1].w : pa[0].w);
            }
            #pragma unroll
            for (int l = 0; l < 2; l++) {
                int idx = tid + l * 256;
                int kr  = idx >> 5, nv = idx & 31;
                *(float4*)&Bs[nbuf][kr][nv * 4] = pb[l];
            }
        }
        __syncthreads();
    }

    // ---- epilogue ----
    const int row0 = bm + ty * 8;
    const int col0 = bn + tx * 8;

    float bv[8];
    *(float4*)&bv[0] = *(const float4*)(bias + col0);
    *(float4*)&bv[4] = *(const float4*)(bias + col0 + 4);

    if (FUSE_SWIGLU) {
        // col0 is even; pairs (2p, 2p+1) are (glu, lin). Output col = col0/2 + p.
        const int oc = col0 >> 1;
        #pragma unroll
        for (int i = 0; i < 8; i++) {
            float o[4];
            #pragma unroll
            for (int p = 0; p < 4; p++) {
                float g = acc[i][2 * p]     + bv[2 * p];
                float l = acc[i][2 * p + 1] + bv[2 * p + 1];
                g = fminf(g, LIMIT_);
                l = fminf(fmaxf(l, -LIMIT_), LIMIT_);
                float s = 1.0f / (1.0f + __expf(-ALPHA_ * g));
                o[p] = g * s * (l + 1.0f);
            }
            *(float4*)(C + (size_t)(row0 + i) * Cw + oc) = *(float4*)o;
        }
    } else {
        #pragma unroll
        for (int i = 0; i < 8; i++) {
            float o[8];
            #pragma unroll
            for (int j = 0; j < 8; j++) o[j] = acc[i][j] + bv[j];
            float* cp = C + (size_t)(row0 + i) * Cw + col0;
            *(float4*)(cp)     = *(float4*)&o[0];
            *(float4*)(cp + 4) = *(float4*)&o[4];
        }
    }
}

extern "C" void kernel_launch(void* const* d_in, const int* in_sizes, int n_in,
                              void* d_out, int out_size)
{
    (void)in_sizes; (void)n_in; (void)out_size;
    const float* x  = (const float*)d_in[0];   // [E,T,D]
    const float* w1 = (const float*)d_in[1];   // [E,D,2D]
    const float* b1 = (const float*)d_in[2];   // [E,2D]
    const float* w2 = (const float*)d_in[3];   // [E,D,D]
    const float* b2 = (const float*)d_in[4];   // [E,D]
    float* out = (float*)d_out;                // [E,T,D]

    float* act = nullptr;
    cudaGetSymbolAddress((void**)&act, g_act); // no allocation; just address query

    dim3 block(256);

    // GEMM1 + bias + SwiGLU -> act  (M=T, N=2D, K=D)
    dim3 grid1(F_ / BN, T_ / BM, E_);
    sgemm_kernel<true><<<grid1, block>>>(x, w1, b1, act, T_, F_, D_);

    // GEMM2 + bias -> out  (M=T, N=D, K=D)
    dim3 grid2(D_ / BN, T_ / BM, E_);
    sgemm_kernel<false><<<grid2, block>>>(act, w2, b2, out, T_, D_, D_);
}

// round 4
// speedup vs baseline: 3.0038x; 3.0038x over previous
#include <cuda_runtime.h>
#include <cstdint>

// ============================================================================
// GroupedExperts: out = swiglu(x@W1+b1) @ W2 + b2   (E=8, T=2048, D=2048)
// R4: mma.sync m16n8k8 tf32 pipeline; fixes R3's 4x-underloaded B tile
// (producer now covers all 32x128 B elements). SwiGLU fused in GEMM1 epilogue.
// ============================================================================

namespace {
constexpr int E_ = 8;
constexpr int T_ = 2048;
constexpr int D_ = 2048;
constexpr int F_ = 4096;

constexpr int BM = 128, BN = 128, BK = 32;
constexpr int STAGES = 4;
constexpr int NT = D_ / BK;                 // 64 (K = 2048 in both GEMMs)

constexpr int BNP = 132;                    // padded B row (floats) — conflict-free
constexpr int A_STAGE_B = BM * BK * 4;      // 16384 bytes
constexpr int B_STAGE_B = BK * BNP * 4;     // 16896 bytes
constexpr int STAGE_B   = A_STAGE_B + B_STAGE_B;   // 33280 (128B multiple)
constexpr int SMEM_BYTES = STAGES * STAGE_B + 128;

constexpr float ALPHA_ = 1.702f;
constexpr float LIMIT_ = 7.0f;
}

__device__ float g_act[(size_t)E_ * T_ * D_];   // 128 MiB intermediate

// ---------------- PTX helpers (all plain-target instructions) ----------------
__device__ __forceinline__ uint32_t smem_u32(const void* p) {
    uint32_t a;
    asm("{ .reg .u64 t; cvta.to.shared.u64 t, %1; cvt.u32.u64 %0, t; }" : "=r"(a) : "l"(p));
    return a;
}
__device__ __forceinline__ uint32_t swzA(uint32_t row, uint32_t ch) {
    // 128B rows, 16B chunks, SW128: chunk ^= row&7
    return row * 128u + ((ch ^ (row & 7u)) * 16u);
}
__device__ __forceinline__ void cpasync16(uint32_t dst, const void* src) {
    asm volatile("cp.async.cg.shared.global [%0], [%1], 16;" :: "r"(dst), "l"(src) : "memory");
}
__device__ __forceinline__ void cp_commit() {
    asm volatile("cp.async.commit_group;" ::: "memory");
}
template <int N>
__device__ __forceinline__ void cp_wait() {
    asm volatile("cp.async.wait_group %0;" :: "n"(N) : "memory");
}
__device__ __forceinline__ void ldsm_x4(uint32_t* r, uint32_t addr) {
    asm volatile("ldmatrix.sync.aligned.m8n8.x4.shared.b16 {%0,%1,%2,%3}, [%4];"
                 : "=r"(r[0]), "=r"(r[1]), "=r"(r[2]), "=r"(r[3]) : "r"(addr));
}
__device__ __forceinline__ uint32_t lds32(uint32_t addr) {
    uint32_t v;
    asm volatile("ld.shared.b32 %0, [%1];" : "=r"(v) : "r"(addr));
    return v;
}
__device__ __forceinline__ uint32_t to_tf32(uint32_t x) {
    uint32_t t;
    asm("cvt.rna.tf32.f32 %0, %1;" : "=r"(t) : "f"(__uint_as_float(x)));
    return t;
}
__device__ __forceinline__ void mma_tf32(float* c, const uint32_t* a, const uint32_t* b) {
    asm volatile(
        "mma.sync.aligned.m16n8k8.row.col.f32.tf32.tf32.f32 "
        "{%0,%1,%2,%3}, {%4,%5,%6,%7}, {%8,%9}, {%0,%1,%2,%3};"
        : "+f"(c[0]), "+f"(c[1]), "+f"(c[2]), "+f"(c[3])
        : "r"(a[0]), "r"(a[1]), "r"(a[2]), "r"(a[3]), "r"(b[0]), "r"(b[1]));
}

// ----------------------------------------------------------------------------
// C 128x128 tile = A[128, K] @ W[K, NTOT slice 128]  (+bias, optional SwiGLU)
// A row-major (K contiguous), W row-major (N contiguous).
// ----------------------------------------------------------------------------
template <bool FUSE, int NTOT>
__global__ __launch_bounds__(256)
void mma_gemm_kernel(const float* __restrict__ Ag,
                     const float* __restrict__ Wg,
                     const float* __restrict__ biasg,
                     float* __restrict__ Cg)
{
    extern __shared__ float dsm[];
    const int tid  = threadIdx.x;
    const int wid  = tid >> 5;
    const int lane = tid & 31;
    const int e  = blockIdx.z;
    const int bm = blockIdx.y * BM;
    const int bn = blockIdx.x * BN;

    const float* Ae = Ag + ((size_t)e * T_ + bm) * D_;
    const float* We = Wg + (size_t)e * D_ * NTOT + bn;
    const float* Be = biasg + (size_t)e * NTOT + bn;

    const uint32_t s0 = (smem_u32(dsm) + 127u) & ~127u;

    // producer: A = 1024 x 16B chunks (4/thread), B = 1024 x 16B chunks (4/thread)
    auto produce = [&](int kt) {
        const int s = kt % STAGES;
        const uint32_t sA = s0 + s * STAGE_B;
        const uint32_t sB = sA + A_STAGE_B;
        const float* a_src = Ae + kt * BK;
        const float* b_src = We + (size_t)(kt * BK) * NTOT;
        #pragma unroll
        for (int i = 0; i < 4; i++) {
            int id = tid + 256 * i;
            int row = id >> 3, c = id & 7;
            cpasync16(sA + swzA(row, c), a_src + (size_t)row * D_ + c * 4);
        }
        #pragma unroll
        for (int i = 0; i < 4; i++) {
            int id = tid + 256 * i;
            int k = id >> 5, c = id & 31;            // 32 k-rows x 32 col-chunks
            cpasync16(sB + (uint32_t)(k * BNP + c * 4) * 4,
                      b_src + (size_t)k * NTOT + c * 4);
        }
        cp_commit();
    };

    #pragma unroll
    for (int kt = 0; kt < STAGES - 1; kt++) produce(kt);

    const int wm = (wid >> 2) * 64;   // warp m offset (0/64)
    const int wn = (wid & 3) * 32;    // warp n offset (0/32/64/96)

    float acc[4][4][4];
    #pragma unroll
    for (int mi = 0; mi < 4; mi++)
        #pragma unroll
        for (int ni = 0; ni < 4; ni++)
            #pragma unroll
            for (int v = 0; v < 4; v++) acc[mi][ni][v] = 0.0f;

    // ldmatrix lane->address pieces: lanes 0-15 -> rows, k-chunk lo;
    // lanes 16-31 -> rows, k-chunk hi (tf32 m16k8 via 4x m8n8.b16 matrices)
    const int lrow = lane & 15;
    const int lchx = lane >> 4;

    for (int kt = 0; kt < NT; kt++) {
        cp_wait<STAGES - 2>();
        __syncthreads();
        if (kt + STAGES - 1 < NT) produce(kt + STAGES - 1);

        const uint32_t sA = s0 + (kt % STAGES) * STAGE_B;
        const uint32_t sB = sA + A_STAGE_B;

        #pragma unroll
        for (int ks = 0; ks < 4; ks++) {
            uint32_t a[4][4];
            #pragma unroll
            for (int mi = 0; mi < 4; mi++) {
                ldsm_x4(a[mi], sA + swzA(wm + mi * 16 + lrow, 2 * ks + lchx));
                #pragma unroll
                for (int v = 0; v < 4; v++) a[mi][v] = to_tf32(a[mi][v]);
            }
            uint32_t b[4][2];
            #pragma unroll
            for (int ni = 0; ni < 4; ni++) {
                uint32_t base = sB + (uint32_t)((ks * 8 + (lane & 3)) * BNP
                                                + wn + ni * 8 + (lane >> 2)) * 4;
                b[ni][0] = to_tf32(lds32(base));
                b[ni][1] = to_tf32(lds32(base + 4u * BNP * 4u));
            }
            #pragma unroll
            for (int mi = 0; mi < 4; mi++)
                #pragma unroll
                for (int ni = 0; ni < 4; ni++)
                    mma_tf32(acc[mi][ni], a[mi], b[ni]);
        }
    }

    // ------------------------------ epilogue ------------------------------
    // acc frag (m16n8): c0,c1 -> row g=lane>>2, cols 2*(lane&3)+{0,1};
    //                   c2,c3 -> row g+8, same cols.
    #pragma unroll
    for (int ni = 0; ni < 4; ni++) {
        const int cl = wn + ni * 8 + 2 * (lane & 3);    // even col within tile
        const float b_e = Be[cl];
        const float b_o = Be[cl + 1];
        #pragma unroll
        for (int mi = 0; mi < 4; mi++) {
            const int r0 = bm + wm + mi * 16 + (lane >> 2);
            #pragma unroll
            for (int h = 0; h < 2; h++) {               // row half: r0, r0+8
                const float v0 = acc[mi][ni][2 * h + 0] + b_e;
                const float v1 = acc[mi][ni][2 * h + 1] + b_o;
                const size_t row = (size_t)e * T_ + r0 + 8 * h;
                if (FUSE) {
                    float g = fminf(v0, LIMIT_);
                    float l = fminf(fmaxf(v1, -LIMIT_), LIMIT_);
                    float sg = 1.0f / (1.0f + __expf(-ALPHA_ * g));
                    Cg[row * D_ + ((bn + cl) >> 1)] = g * sg * (l + 1.0f);
                } else {
                    float2 o = make_float2(v0, v1);
                    *(float2*)(Cg + row * D_ + bn + cl) = o;
                }
            }
        }
    }
}

// ----------------------------------------------------------------------------
extern "C" void kernel_launch(void* const* d_in, const int* in_sizes, int n_in,
                              void* d_out, int out_size)
{
    (void)in_sizes; (void)n_in; (void)out_size;
    const float* x  = (const float*)d_in[0];
    const float* w1 = (const float*)d_in[1];
    const float* b1 = (const float*)d_in[2];
    const float* w2 = (const float*)d_in[3];
    const float* b2 = (const float*)d_in[4];
    float* out = (float*)d_out;

    float* act = nullptr;
    cudaGetSymbolAddress((void**)&act, g_act);

    static bool attr_done = false;
    if (!attr_done) {
        cudaFuncSetAttribute(mma_gemm_kernel<true,  F_>,
                             cudaFuncAttributeMaxDynamicSharedMemorySize, SMEM_BYTES);
        cudaFuncSetAttribute(mma_gemm_kernel<false, D_>,
                             cudaFuncAttributeMaxDynamicSharedMemorySize, SMEM_BYTES);
        attr_done = true;
    }

    // GEMM1 + bias + SwiGLU -> act   (M=2048, N=4096, K=2048 per expert)
    dim3 g1(F_ / BN, T_ / BM, E_);
    mma_gemm_kernel<true,  F_><<<g1, 256, SMEM_BYTES>>>(x, w1, b1, act);

    // GEMM2 + bias -> out            (M=2048, N=2048, K=2048 per expert)
    dim3 g2(D_ / BN, T_ / BM, E_);
    mma_gemm_kernel<false, D_><<<g2, 256, SMEM_BYTES>>>(act, w2, b2, out);
}

// round 5
// speedup vs baseline: 3.5137x; 1.1698x over previous
#include <cuda_runtime.h>
#include <cstdint>

// ============================================================================
// GroupedExperts: out = swiglu(x@W1+b1) @ W2 + b2   (E=8, T=2048, D=2048)
// R5: same verified mma.sync tf32 pipeline as R4, but 3 stages + 2 CTAs/SM
// (occ 12.5% -> 25%) to fix the issue-starvation ncu exposed.
// ============================================================================

namespace {
constexpr int E_ = 8;
constexpr int T_ = 2048;
constexpr int D_ = 2048;
constexpr int F_ = 4096;

constexpr int BM = 128, BN = 128, BK = 32;
constexpr int STAGES = 3;
constexpr int NT = D_ / BK;                 // 64 (K = 2048 in both GEMMs)

constexpr int BNP = 132;                    // padded B row (floats) — conflict-free
constexpr int A_STAGE_B = BM * BK * 4;      // 16384 bytes
constexpr int B_STAGE_B = BK * BNP * 4;     // 16896 bytes
constexpr int STAGE_B   = A_STAGE_B + B_STAGE_B;   // 33280 (128B multiple)
constexpr int SMEM_BYTES = STAGES * STAGE_B + 128; // ~99.9 KB -> 2 CTAs/SM

constexpr float ALPHA_ = 1.702f;
constexpr float LIMIT_ = 7.0f;
}

__device__ float g_act[(size_t)E_ * T_ * D_];   // 128 MiB intermediate

// ---------------- PTX helpers (all plain-target instructions) ----------------
__device__ __forceinline__ uint32_t smem_u32(const void* p) {
    uint32_t a;
    asm("{ .reg .u64 t; cvta.to.shared.u64 t, %1; cvt.u32.u64 %0, t; }" : "=r"(a) : "l"(p));
    return a;
}
__device__ __forceinline__ uint32_t swzA(uint32_t row, uint32_t ch) {
    // 128B rows, 16B chunks, SW128: chunk ^= row&7
    return row * 128u + ((ch ^ (row & 7u)) * 16u);
}
__device__ __forceinline__ void cpasync16(uint32_t dst, const void* src) {
    asm volatile("cp.async.cg.shared.global [%0], [%1], 16;" :: "r"(dst), "l"(src) : "memory");
}
__device__ __forceinline__ void cp_commit() {
    asm volatile("cp.async.commit_group;" ::: "memory");
}
template <int N>
__device__ __forceinline__ void cp_wait() {
    asm volatile("cp.async.wait_group %0;" :: "n"(N) : "memory");
}
__device__ __forceinline__ void ldsm_x4(uint32_t* r, uint32_t addr) {
    asm volatile("ldmatrix.sync.aligned.m8n8.x4.shared.b16 {%0,%1,%2,%3}, [%4];"
                 : "=r"(r[0]), "=r"(r[1]), "=r"(r[2]), "=r"(r[3]) : "r"(addr));
}
__device__ __forceinline__ uint32_t lds32(uint32_t addr) {
    uint32_t v;
    asm volatile("ld.shared.b32 %0, [%1];" : "=r"(v) : "r"(addr));
    return v;
}
__device__ __forceinline__ uint32_t to_tf32(uint32_t x) {
    uint32_t t;
    asm("cvt.rna.tf32.f32 %0, %1;" : "=r"(t) : "f"(__uint_as_float(x)));
    return t;
}
__device__ __forceinline__ void mma_tf32(float* c, const uint32_t* a, const uint32_t* b) {
    asm volatile(
        "mma.sync.aligned.m16n8k8.row.col.f32.tf32.tf32.f32 "
        "{%0,%1,%2,%3}, {%4,%5,%6,%7}, {%8,%9}, {%0,%1,%2,%3};"
        : "+f"(c[0]), "+f"(c[1]), "+f"(c[2]), "+f"(c[3])
        : "r"(a[0]), "r"(a[1]), "r"(a[2]), "r"(a[3]), "r"(b[0]), "r"(b[1]));
}

// ----------------------------------------------------------------------------
// C 128x128 tile = A[128, K] @ W[K, NTOT slice 128]  (+bias, optional SwiGLU)
// A row-major (K contiguous), W row-major (N contiguous).
// ----------------------------------------------------------------------------
template <bool FUSE, int NTOT>
__global__ __launch_bounds__(256, 2)
void mma_gemm_kernel(const float* __restrict__ Ag,
                     const float* __restrict__ Wg,
                     const float* __restrict__ biasg,
                     float* __restrict__ Cg)
{
    extern __shared__ float dsm[];
    const int tid  = threadIdx.x;
    const int wid  = tid >> 5;
    const int lane = tid & 31;
    const int e  = blockIdx.z;
    const int bm = blockIdx.y * BM;
    const int bn = blockIdx.x * BN;

    const float* Ae = Ag + ((size_t)e * T_ + bm) * D_;
    const float* We = Wg + (size_t)e * D_ * NTOT + bn;
    const float* Be = biasg + (size_t)e * NTOT + bn;

    const uint32_t s0 = (smem_u32(dsm) + 127u) & ~127u;

    // producer: A = 1024 x 16B chunks (4/thread), B = 1024 x 16B chunks (4/thread)
    auto produce = [&](int kt) {
        const int s = kt % STAGES;
        const uint32_t sA = s0 + s * STAGE_B;
        const uint32_t sB = sA + A_STAGE_B;
        const float* a_src = Ae + kt * BK;
        const float* b_src = We + (size_t)(kt * BK) * NTOT;
        #pragma unroll
        for (int i = 0; i < 4; i++) {
            int id = tid + 256 * i;
            int row = id >> 3, c = id & 7;
            cpasync16(sA + swzA(row, c), a_src + (size_t)row * D_ + c * 4);
        }
        #pragma unroll
        for (int i = 0; i < 4; i++) {
            int id = tid + 256 * i;
            int k = id >> 5, c = id & 31;            // 32 k-rows x 32 col-chunks
            cpasync16(sB + (uint32_t)(k * BNP + c * 4) * 4,
                      b_src + (size_t)k * NTOT + c * 4);
        }
        cp_commit();
    };

    #pragma unroll
    for (int kt = 0; kt < STAGES - 1; kt++) produce(kt);

    const int wm = (wid >> 2) * 64;   // warp m offset (0/64)
    const int wn = (wid & 3) * 32;    // warp n offset (0/32/64/96)

    float acc[4][4][4];
    #pragma unroll
    for (int mi = 0; mi < 4; mi++)
        #pragma unroll
        for (int ni = 0; ni < 4; ni++)
            #pragma unroll
            for (int v = 0; v < 4; v++) acc[mi][ni][v] = 0.0f;

    // ldmatrix lane->address pieces: lanes 0-15 -> rows, k-chunk lo;
    // lanes 16-31 -> rows, k-chunk hi (tf32 m16k8 via 4x m8n8.b16 matrices)
    const int lrow = lane & 15;
    const int lchx = lane >> 4;

    for (int kt = 0; kt < NT; kt++) {
        cp_wait<STAGES - 2>();
        __syncthreads();
        if (kt + STAGES - 1 < NT) produce(kt + STAGES - 1);

        const uint32_t sA = s0 + (kt % STAGES) * STAGE_B;
        const uint32_t sB = sA + A_STAGE_B;

        #pragma unroll
        for (int ks = 0; ks < 4; ks++) {
            uint32_t a[4][4];
            #pragma unroll
            for (int mi = 0; mi < 4; mi++) {
                ldsm_x4(a[mi], sA + swzA(wm + mi * 16 + lrow, 2 * ks + lchx));
                #pragma unroll
                for (int v = 0; v < 4; v++) a[mi][v] = to_tf32(a[mi][v]);
            }
            uint32_t b[4][2];
            #pragma unroll
            for (int ni = 0; ni < 4; ni++) {
                uint32_t base = sB + (uint32_t)((ks * 8 + (lane & 3)) * BNP
                                                + wn + ni * 8 + (lane >> 2)) * 4;
                b[ni][0] = to_tf32(lds32(base));
                b[ni][1] = to_tf32(lds32(base + 4u * BNP * 4u));
            }
            #pragma unroll
            for (int mi = 0; mi < 4; mi++)
                #pragma unroll
                for (int ni = 0; ni < 4; ni++)
                    mma_tf32(acc[mi][ni], a[mi], b[ni]);
        }
    }

    // ------------------------------ epilogue ------------------------------
    // acc frag (m16n8): c0,c1 -> row g=lane>>2, cols 2*(lane&3)+{0,1};
    //                   c2,c3 -> row g+8, same cols.
    #pragma unroll
    for (int ni = 0; ni < 4; ni++) {
        const int cl = wn + ni * 8 + 2 * (lane & 3);    // even col within tile
        const float b_e = Be[cl];
        const float b_o = Be[cl + 1];
        #pragma unroll
        for (int mi = 0; mi < 4; mi++) {
            const int r0 = bm + wm + mi * 16 + (lane >> 2);
            #pragma unroll
            for (int h = 0; h < 2; h++) {               // row half: r0, r0+8
                const float v0 = acc[mi][ni][2 * h + 0] + b_e;
                const float v1 = acc[mi][ni][2 * h + 1] + b_o;
                const size_t row = (size_t)e * T_ + r0 + 8 * h;
                if (FUSE) {
                    float g = fminf(v0, LIMIT_);
                    float l = fminf(fmaxf(v1, -LIMIT_), LIMIT_);
                    float sg = 1.0f / (1.0f + __expf(-ALPHA_ * g));
                    Cg[row * D_ + ((bn + cl) >> 1)] = g * sg * (l + 1.0f);
                } else {
                    float2 o = make_float2(v0, v1);
                    *(float2*)(Cg + row * D_ + bn + cl) = o;
                }
            }
        }
    }
}

// ----------------------------------------------------------------------------
extern "C" void kernel_launch(void* const* d_in, const int* in_sizes, int n_in,
                              void* d_out, int out_size)
{
    (void)in_sizes; (void)n_in; (void)out_size;
    const float* x  = (const float*)d_in[0];
    const float* w1 = (const float*)d_in[1];
    const float* b1 = (const float*)d_in[2];
    const float* w2 = (const float*)d_in[3];
    const float* b2 = (const float*)d_in[4];
    float* out = (float*)d_out;

    float* act = nullptr;
    cudaGetSymbolAddress((void**)&act, g_act);

    static bool attr_done = false;
    if (!attr_done) {
        cudaFuncSetAttribute(mma_gemm_kernel<true,  F_>,
                             cudaFuncAttributeMaxDynamicSharedMemorySize, SMEM_BYTES);
        cudaFuncSetAttribute(mma_gemm_kernel<false, D_>,
                             cudaFuncAttributeMaxDynamicSharedMemorySize, SMEM_BYTES);
        attr_done = true;
    }

    // GEMM1 + bias + SwiGLU -> act   (M=2048, N=4096, K=2048 per expert)
    dim3 g1(F_ / BN, T_ / BM, E_);
    mma_gemm_kernel<true,  F_><<<g1, 256, SMEM_BYTES>>>(x, w1, b1, act);

    // GEMM2 + bias -> out            (M=2048, N=2048, K=2048 per expert)
    dim3 g2(D_ / BN, T_ / BM, E_);
    mma_gemm_kernel<false, D_><<<g2, 256, SMEM_BYTES>>>(act, w2, b2, out);
}

// round 6
// speedup vs baseline: 3.8974x; 1.1092x over previous
#include <cuda_runtime.h>
#include <cstdint>

// ============================================================================
// GroupedExperts: out = swiglu(x@W1+b1) @ W2 + b2   (E=8, T=2048, D=2048)
// R6: mma.sync tf32 pipeline (verified R4/R5), with ALL tf32 rounding hoisted
// out of the mainloop: a pre-pass rounds x/W1/W2 into scratch, GEMM1 epilogue
// stores act pre-rounded. Mainloop = ldsm/lds + mma only.
// ============================================================================

namespace {
constexpr int E_ = 8;
constexpr int T_ = 2048;
constexpr int D_ = 2048;
constexpr int F_ = 4096;

constexpr int BM = 128, BN = 128, BK = 32;
constexpr int STAGES = 3;
constexpr int NT = D_ / BK;                 // 64 (K = 2048 in both GEMMs)

constexpr int BNP = 132;                    // padded B row (floats) — conflict-free
constexpr int A_STAGE_B = BM * BK * 4;      // 16384 bytes
constexpr int B_STAGE_B = BK * BNP * 4;     // 16896 bytes
constexpr int STAGE_B   = A_STAGE_B + B_STAGE_B;   // 33280
constexpr int SMEM_BYTES = STAGES * STAGE_B + 128; // ~99.9 KB -> 2 CTAs/SM

constexpr float ALPHA_ = 1.702f;
constexpr float LIMIT_ = 7.0f;
}

// scratch: rounded inputs + intermediate activation (no allocations allowed)
__device__ float g_act[(size_t)E_ * T_ * D_];   // 128 MiB (stored tf32-rounded)
__device__ float g_xr [(size_t)E_ * T_ * D_];   // 128 MiB
__device__ float g_w1r[(size_t)E_ * D_ * F_];   // 256 MiB
__device__ float g_w2r[(size_t)E_ * D_ * D_];   // 128 MiB

// ---------------- PTX helpers ----------------
__device__ __forceinline__ uint32_t smem_u32(const void* p) {
    uint32_t a;
    asm("{ .reg .u64 t; cvta.to.shared.u64 t, %1; cvt.u32.u64 %0, t; }" : "=r"(a) : "l"(p));
    return a;
}
__device__ __forceinline__ uint32_t swzA(uint32_t row, uint32_t ch) {
    return row * 128u + ((ch ^ (row & 7u)) * 16u);
}
__device__ __forceinline__ void cpasync16(uint32_t dst, const void* src) {
    asm volatile("cp.async.cg.shared.global [%0], [%1], 16;" :: "r"(dst), "l"(src) : "memory");
}
__device__ __forceinline__ void cp_commit() {
    asm volatile("cp.async.commit_group;" ::: "memory");
}
template <int N>
__device__ __forceinline__ void cp_wait() {
    asm volatile("cp.async.wait_group %0;" :: "n"(N) : "memory");
}
__device__ __forceinline__ void ldsm_x4(uint32_t* r, uint32_t addr) {
    asm volatile("ldmatrix.sync.aligned.m8n8.x4.shared.b16 {%0,%1,%2,%3}, [%4];"
                 : "=r"(r[0]), "=r"(r[1]), "=r"(r[2]), "=r"(r[3]) : "r"(addr));
}
__device__ __forceinline__ uint32_t lds32(uint32_t addr) {
    uint32_t v;
    asm volatile("ld.shared.b32 %0, [%1];" : "=r"(v) : "r"(addr));
    return v;
}
__device__ __forceinline__ float to_tf32_f(float x) {
    uint32_t t;
    asm("cvt.rna.tf32.f32 %0, %1;" : "=r"(t) : "f"(x));
    return __uint_as_float(t);
}
__device__ __forceinline__ void mma_tf32(float* c, const uint32_t* a, const uint32_t* b) {
    asm volatile(
        "mma.sync.aligned.m16n8k8.row.col.f32.tf32.tf32.f32 "
        "{%0,%1,%2,%3}, {%4,%5,%6,%7}, {%8,%9}, {%0,%1,%2,%3};"
        : "+f"(c[0]), "+f"(c[1]), "+f"(c[2]), "+f"(c[3])
        : "r"(a[0]), "r"(a[1]), "r"(a[2]), "r"(a[3]), "r"(b[0]), "r"(b[1]));
}

// ---------------- pre-pass: round fp32 -> tf32(rna) bits ----------------
__global__ void round_tf32_kernel(const float4* __restrict__ src,
                                  float4* __restrict__ dst, int n4)
{
    int i = blockIdx.x * blockDim.x + threadIdx.x;
    const int stride = gridDim.x * blockDim.x;
    for (; i < n4; i += stride) {
        float4 v = src[i];
        v.x = to_tf32_f(v.x); v.y = to_tf32_f(v.y);
        v.z = to_tf32_f(v.z); v.w = to_tf32_f(v.w);
        dst[i] = v;
    }
}

// ----------------------------------------------------------------------------
// C 128x128 tile = A[128, K] @ W[K, NTOT slice 128]  (+bias, optional SwiGLU)
// A row-major (K contiguous, pre-rounded). W row-major (N contiguous, pre-rounded).
// ----------------------------------------------------------------------------
template <bool FUSE, int NTOT>
__global__ __launch_bounds__(256, 2)
void mma_gemm_kernel(const float* __restrict__ Ag,
                     const float* __restrict__ Wg,
                     const float* __restrict__ biasg,
                     float* __restrict__ Cg)
{
    extern __shared__ float dsm[];
    const int tid  = threadIdx.x;
    const int wid  = tid >> 5;
    const int lane = tid & 31;
    const int e  = blockIdx.z;
    const int bm = blockIdx.y * BM;
    const int bn = blockIdx.x * BN;

    const float* Ae = Ag + ((size_t)e * T_ + bm) * D_;
    const float* We = Wg + (size_t)e * D_ * NTOT + bn;
    const float* Be = biasg + (size_t)e * NTOT + bn;

    const uint32_t s0 = (smem_u32(dsm) + 127u) & ~127u;
    const uint32_t sEnd = s0 + STAGES * STAGE_B;

    // --- precomputed per-thread producer offsets ---
    uint32_t aOff[4], bOff[4];
    uint32_t aG[4], bG[4];
    #pragma unroll
    for (int i = 0; i < 4; i++) {
        int id = tid + 256 * i;
        int row = id >> 3, c = id & 7;
        aOff[i] = swzA(row, c);
        aG[i]   = (uint32_t)row * D_ + c * 4;
        int k = id >> 5, cc = id & 31;
        bOff[i] = (uint32_t)(k * BNP + cc * 4) * 4;
        bG[i]   = (uint32_t)k * NTOT + cc * 4;
    }

    const float* aSrc = Ae;
    const float* bSrc = We;
    uint32_t prodBase = s0;
    auto produce = [&]() {
        #pragma unroll
        for (int i = 0; i < 4; i++) cpasync16(prodBase + aOff[i], aSrc + aG[i]);
        const uint32_t pb = prodBase + A_STAGE_B;
        #pragma unroll
        for (int i = 0; i < 4; i++) cpasync16(pb + bOff[i], bSrc + bG[i]);
        cp_commit();
        aSrc += BK;
        bSrc += (size_t)BK * NTOT;
        prodBase += STAGE_B;
        if (prodBase == sEnd) prodBase = s0;
    };

    produce();
    produce();

    const int wm = (wid >> 2) * 64;   // warp m offset (0/64)
    const int wn = (wid & 3) * 32;    // warp n offset (0/32/64/96)

    float acc[4][4][4];
    #pragma unroll
    for (int mi = 0; mi < 4; mi++)
        #pragma unroll
        for (int ni = 0; ni < 4; ni++)
            #pragma unroll
            for (int v = 0; v < 4; v++) acc[mi][ni][v] = 0.0f;

    const int lrow = lane & 15;
    const int lchx = lane >> 4;

    uint32_t consBase = s0;
    for (int kt = 0; kt < NT; kt++) {
        cp_wait<STAGES - 2>();
        __syncthreads();
        if (kt + STAGES - 1 < NT) produce();

        const uint32_t sA = consBase;
        const uint32_t sB = consBase + A_STAGE_B;

        #pragma unroll
        for (int ks = 0; ks < 4; ks++) {
            uint32_t a[4][4];
            #pragma unroll
            for (int mi = 0; mi < 4; mi++)
                ldsm_x4(a[mi], sA + swzA(wm + mi * 16 + lrow, 2 * ks + lchx));
            uint32_t b[4][2];
            #pragma unroll
            for (int ni = 0; ni < 4; ni++) {
                uint32_t base = sB + (uint32_t)((ks * 8 + (lane & 3)) * BNP
                                                + wn + ni * 8 + (lane >> 2)) * 4;
                b[ni][0] = lds32(base);
                b[ni][1] = lds32(base + 4u * BNP * 4u);
            }
            #pragma unroll
            for (int mi = 0; mi < 4; mi++)
                #pragma unroll
                for (int ni = 0; ni < 4; ni++)
                    mma_tf32(acc[mi][ni], a[mi], b[ni]);
        }

        consBase += STAGE_B;
        if (consBase == sEnd) consBase = s0;
    }

    // ------------------------------ epilogue ------------------------------
    #pragma unroll
    for (int ni = 0; ni < 4; ni++) {
        const int cl = wn + ni * 8 + 2 * (lane & 3);    // even col within tile
        const float b_e = Be[cl];
        const float b_o = Be[cl + 1];
        #pragma unroll
        for (int mi = 0; mi < 4; mi++) {
            const int r0 = bm + wm + mi * 16 + (lane >> 2);
            #pragma unroll
            for (int h = 0; h < 2; h++) {
                const float v0 = acc[mi][ni][2 * h + 0] + b_e;
                const float v1 = acc[mi][ni][2 * h + 1] + b_o;
                const size_t row = (size_t)e * T_ + r0 + 8 * h;
                if (FUSE) {
                    float g = fminf(v0, LIMIT_);
                    float l = fminf(fmaxf(v1, -LIMIT_), LIMIT_);
                    float sg = 1.0f / (1.0f + __expf(-ALPHA_ * g));
                    // store pre-rounded to tf32: GEMM2 consumes raw bits
                    Cg[row * D_ + ((bn + cl) >> 1)] = to_tf32_f(g * sg * (l + 1.0f));
                } else {
                    float2 o = make_float2(v0, v1);
                    *(float2*)(Cg + row * D_ + bn + cl) = o;
                }
            }
        }
    }
}

// ----------------------------------------------------------------------------
extern "C" void kernel_launch(void* const* d_in, const int* in_sizes, int n_in,
                              void* d_out, int out_size)
{
    (void)in_sizes; (void)n_in; (void)out_size;
    const float* x  = (const float*)d_in[0];
    const float* w1 = (const float*)d_in[1];
    const float* b1 = (const float*)d_in[2];
    const float* w2 = (const float*)d_in[3];
    const float* b2 = (const float*)d_in[4];
    float* out = (float*)d_out;

    float *act, *xr, *w1r, *w2r;
    cudaGetSymbolAddress((void**)&act, g_act);
    cudaGetSymbolAddress((void**)&xr,  g_xr);
    cudaGetSymbolAddress((void**)&w1r, g_w1r);
    cudaGetSymbolAddress((void**)&w2r, g_w2r);

    static bool attr_done = false;
    if (!attr_done) {
        cudaFuncSetAttribute(mma_gemm_kernel<true,  F_>,
                             cudaFuncAttributeMaxDynamicSharedMemorySize, SMEM_BYTES);
        cudaFuncSetAttribute(mma_gemm_kernel<false, D_>,
                             cudaFuncAttributeMaxDynamicSharedMemorySize, SMEM_BYTES);
        attr_done = true;
    }

    // pre-pass: round inputs to tf32 (rna) once
    const int nx  = E_ * T_ * D_ / 4;
    const int nw1 = E_ * D_ * F_ / 4;
    const int nw2 = E_ * D_ * D_ / 4;
    round_tf32_kernel<<<8192, 256>>>((const float4*)x,  (float4*)xr,  nx);
    round_tf32_kernel<<<8192, 256>>>((const float4*)w1, (float4*)w1r, nw1);
    round_tf32_kernel<<<8192, 256>>>((const float4*)w2, (float4*)w2r, nw2);

    // GEMM1 + bias + SwiGLU -> act (pre-rounded)   (M=2048, N=4096, K=2048)
    dim3 g1(F_ / BN, T_ / BM, E_);
    mma_gemm_kernel<true,  F_><<<g1, 256, SMEM_BYTES>>>(xr, w1r, b1, act);

    // GEMM2 + bias -> out                          (M=2048, N=2048, K=2048)
    dim3 g2(D_ / BN, T_ / BM, E_);
    mma_gemm_kernel<false, D_><<<g2, 256, SMEM_BYTES>>>(act, w2r, b2, out);
}

// round 7
// speedup vs baseline: 4.2516x; 1.0909x over previous
#include <cuda_runtime.h>
#include <cstdint>

// ============================================================================
// GroupedExperts: out = swiglu(x@W1+b1) @ W2 + b2   (E=8, T=2048, D=2048)
// R7: R6 pipeline + (1) BNP 132->136 fixing 2-way bank conflicts on B lds.32,
// (2) B-fragment double buffering across ks steps, hoisted frag addresses.
// Pre-pass rounds x/W1/W2 to tf32; act stored pre-rounded by GEMM1 epilogue.
// ============================================================================

namespace {
constexpr int E_ = 8;
constexpr int T_ = 2048;
constexpr int D_ = 2048;
constexpr int F_ = 4096;

constexpr int BM = 128, BN = 128, BK = 32;
constexpr int STAGES = 3;
constexpr int NT = D_ / BK;                 // 64 (K = 2048 in both GEMMs)

constexpr int BNP = 136;                    // 136 % 32 == 8 -> conflict-free B lds
constexpr int A_STAGE_B = BM * BK * 4;      // 16384 bytes
constexpr int B_STAGE_B = BK * BNP * 4;     // 17408 bytes
constexpr int STAGE_B   = A_STAGE_B + B_STAGE_B;   // 33792
constexpr int SMEM_BYTES = STAGES * STAGE_B + 128; // ~99.1 KB -> 2 CTAs/SM

constexpr float ALPHA_ = 1.702f;
constexpr float LIMIT_ = 7.0f;
}

// scratch: rounded inputs + intermediate activation (no allocations allowed)
__device__ float g_act[(size_t)E_ * T_ * D_];   // 128 MiB (stored tf32-rounded)
__device__ float g_xr [(size_t)E_ * T_ * D_];   // 128 MiB
__device__ float g_w1r[(size_t)E_ * D_ * F_];   // 256 MiB
__device__ float g_w2r[(size_t)E_ * D_ * D_];   // 128 MiB

// ---------------- PTX helpers ----------------
__device__ __forceinline__ uint32_t smem_u32(const void* p) {
    uint32_t a;
    asm("{ .reg .u64 t; cvta.to.shared.u64 t, %1; cvt.u32.u64 %0, t; }" : "=r"(a) : "l"(p));
    return a;
}
__device__ __forceinline__ uint32_t swzA(uint32_t row, uint32_t ch) {
    return row * 128u + ((ch ^ (row & 7u)) * 16u);
}
__device__ __forceinline__ void cpasync16(uint32_t dst, const void* src) {
    asm volatile("cp.async.cg.shared.global [%0], [%1], 16;" :: "r"(dst), "l"(src) : "memory");
}
__device__ __forceinline__ void cp_commit() {
    asm volatile("cp.async.commit_group;" ::: "memory");
}
template <int N>
__device__ __forceinline__ void cp_wait() {
    asm volatile("cp.async.wait_group %0;" :: "n"(N) : "memory");
}
__device__ __forceinline__ void ldsm_x4(uint32_t* r, uint32_t addr) {
    asm volatile("ldmatrix.sync.aligned.m8n8.x4.shared.b16 {%0,%1,%2,%3}, [%4];"
                 : "=r"(r[0]), "=r"(r[1]), "=r"(r[2]), "=r"(r[3]) : "r"(addr));
}
__device__ __forceinline__ uint32_t lds32(uint32_t addr) {
    uint32_t v;
    asm volatile("ld.shared.b32 %0, [%1];" : "=r"(v) : "r"(addr));
    return v;
}
__device__ __forceinline__ float to_tf32_f(float x) {
    uint32_t t;
    asm("cvt.rna.tf32.f32 %0, %1;" : "=r"(t) : "f"(x));
    return __uint_as_float(t);
}
__device__ __forceinline__ void mma_tf32(float* c, const uint32_t* a, const uint32_t* b) {
    asm volatile(
        "mma.sync.aligned.m16n8k8.row.col.f32.tf32.tf32.f32 "
        "{%0,%1,%2,%3}, {%4,%5,%6,%7}, {%8,%9}, {%0,%1,%2,%3};"
        : "+f"(c[0]), "+f"(c[1]), "+f"(c[2]), "+f"(c[3])
        : "r"(a[0]), "r"(a[1]), "r"(a[2]), "r"(a[3]), "r"(b[0]), "r"(b[1]));
}

// ---------------- pre-pass: round fp32 -> tf32(rna) bits ----------------
__global__ void round_tf32_kernel(const float4* __restrict__ src,
                                  float4* __restrict__ dst, int n4)
{
    int i = blockIdx.x * blockDim.x + threadIdx.x;
    const int stride = gridDim.x * blockDim.x;
    for (; i < n4; i += stride) {
        float4 v = src[i];
        v.x = to_tf32_f(v.x); v.y = to_tf32_f(v.y);
        v.z = to_tf32_f(v.z); v.w = to_tf32_f(v.w);
        dst[i] = v;
    }
}

// ----------------------------------------------------------------------------
// C 128x128 tile = A[128, K] @ W[K, NTOT slice 128]  (+bias, optional SwiGLU)
// ----------------------------------------------------------------------------
template <bool FUSE, int NTOT>
__global__ __launch_bounds__(256, 2)
void mma_gemm_kernel(const float* __restrict__ Ag,
                     const float* __restrict__ Wg,
                     const float* __restrict__ biasg,
                     float* __restrict__ Cg)
{
    extern __shared__ float dsm[];
    const int tid  = threadIdx.x;
    const int wid  = tid >> 5;
    const int lane = tid & 31;
    const int e  = blockIdx.z;
    const int bm = blockIdx.y * BM;
    const int bn = blockIdx.x * BN;

    const float* Ae = Ag + ((size_t)e * T_ + bm) * D_;
    const float* We = Wg + (size_t)e * D_ * NTOT + bn;
    const float* Be = biasg + (size_t)e * NTOT + bn;

    const uint32_t s0 = (smem_u32(dsm) + 127u) & ~127u;
    const uint32_t sEnd = s0 + STAGES * STAGE_B;

    // --- producer state ---
    const int pArow = tid >> 3, pAc = tid & 7;
    const uint32_t pAoff = swzA(pArow, pAc);
    const uint32_t pAg   = (uint32_t)pArow * D_ + pAc * 4;
    const int pBk = tid >> 5, pBc = tid & 31;
    const uint32_t pBoff = (uint32_t)(pBk * BNP + pBc * 4) * 4;
    const uint32_t pBg   = (uint32_t)pBk * NTOT + pBc * 4;

    const float* aSrc = Ae;
    const float* bSrc = We;
    uint32_t prodBase = s0;
    auto produce = [&]() {
        #pragma unroll
        for (int i = 0; i < 4; i++)
            cpasync16(prodBase + pAoff + i * (32u * 128u),
                      aSrc + pAg + (size_t)(32 * i) * D_);
        const uint32_t pb = prodBase + A_STAGE_B;
        #pragma unroll
        for (int i = 0; i < 4; i++)
            cpasync16(pb + pBoff + i * (8u * BNP * 4u),
                      bSrc + pBg + (size_t)(8 * i) * NTOT);
        cp_commit();
        aSrc += BK;
        bSrc += (size_t)BK * NTOT;
        prodBase += STAGE_B;
        if (prodBase == sEnd) prodBase = s0;
    };

    produce();
    produce();

    const int wm = (wid >> 2) * 64;   // warp m offset (0/64)
    const int wn = (wid & 3) * 32;    // warp n offset (0/32/64/96)

    float acc[4][4][4];
    #pragma unroll
    for (int mi = 0; mi < 4; mi++)
        #pragma unroll
        for (int ni = 0; ni < 4; ni++)
            #pragma unroll
            for (int v = 0; v < 4; v++) acc[mi][ni][v] = 0.0f;

    // --- consumer per-thread constants ---
    const int lrow = lane & 15;
    const int lchx = lane >> 4;
    const uint32_t rx = (uint32_t)(lrow & 7);            // swizzle xor for A rows
    uint32_t aRowOff[4];                                  // row*128 per mi
    #pragma unroll
    for (int mi = 0; mi < 4; mi++)
        aRowOff[mi] = (uint32_t)(wm + mi * 16 + lrow) * 128u;
    // B frag base: word (lane&3)*BNP + wn + lane>>2
    const uint32_t bBaseOff = (uint32_t)(((lane & 3) * BNP) + wn + (lane >> 2)) * 4u;

    uint32_t consBase = s0;
    for (int kt = 0; kt < NT; kt++) {
        cp_wait<STAGES - 2>();
        __syncthreads();
        if (kt + STAGES - 1 < NT) produce();

        const uint32_t sA = consBase;
        const uint32_t sB = consBase + A_STAGE_B + bBaseOff;

        uint32_t b[2][4][2];
        #pragma unroll
        for (int ni = 0; ni < 4; ni++) {                 // B frags for ks=0
            uint32_t base = sB + (uint32_t)(ni * 8) * 4u;
            b[0][ni][0] = lds32(base);
            b[0][ni][1] = lds32(base + 4u * BNP * 4u);
        }

        #pragma unroll
        for (int ks = 0; ks < 4; ks++) {
            uint32_t a[4][4];
            #pragma unroll
            for (int mi = 0; mi < 4; mi++) {
                uint32_t ch = ((uint32_t)(2 * ks + lchx) ^ rx) * 16u;
                ldsm_x4(a[mi], sA + aRowOff[mi] + ch);
            }
            if (ks < 3) {
                #pragma unroll
                for (int ni = 0; ni < 4; ni++) {         // prefetch B(ks+1)
                    uint32_t base = sB + (uint32_t)((ks + 1) * 8 * BNP + ni * 8) * 4u;
                    b[(ks + 1) & 1][ni][0] = lds32(base);
                    b[(ks + 1) & 1][ni][1] = lds32(base + 4u * BNP * 4u);
                }
            }
            #pragma unroll
            for (int mi = 0; mi < 4; mi++)
                #pragma unroll
                for (int ni = 0; ni < 4; ni++)
                    mma_tf32(acc[mi][ni], a[mi], b[ks & 1][ni]);
        }

        consBase += STAGE_B;
        if (consBase == sEnd) consBase = s0;
    }

    // ------------------------------ epilogue ------------------------------
    #pragma unroll
    for (int ni = 0; ni < 4; ni++) {
        const int cl = wn + ni * 8 + 2 * (lane & 3);    // even col within tile
        const float b_e = Be[cl];
        const float b_o = Be[cl + 1];
        #pragma unroll
        for (int mi = 0; mi < 4; mi++) {
            const int r0 = bm + wm + mi * 16 + (lane >> 2);
            #pragma unroll
            for (int h = 0; h < 2; h++) {
                const float v0 = acc[mi][ni][2 * h + 0] + b_e;
                const float v1 = acc[mi][ni][2 * h + 1] + b_o;
                const size_t row = (size_t)e * T_ + r0 + 8 * h;
                if (FUSE) {
                    float g = fminf(v0, LIMIT_);
                    float l = fminf(fmaxf(v1, -LIMIT_), LIMIT_);
                    float sg = 1.0f / (1.0f + __expf(-ALPHA_ * g));
                    Cg[row * D_ + ((bn + cl) >> 1)] = to_tf32_f(g * sg * (l + 1.0f));
                } else {
                    float2 o = make_float2(v0, v1);
                    *(float2*)(Cg + row * D_ + bn + cl) = o;
                }
            }
        }
    }
}

// ----------------------------------------------------------------------------
extern "C" void kernel_launch(void* const* d_in, const int* in_sizes, int n_in,
                              void* d_out, int out_size)
{
    (void)in_sizes; (void)n_in; (void)out_size;
    const float* x  = (const float*)d_in[0];
    const float* w1 = (const float*)d_in[1];
    const float* b1 = (const float*)d_in[2];
    const float* w2 = (const float*)d_in[3];
    const float* b2 = (const float*)d_in[4];
    float* out = (float*)d_out;

    float *act, *xr, *w1r, *w2r;
    cudaGetSymbolAddress((void**)&act, g_act);
    cudaGetSymbolAddress((void**)&xr,  g_xr);
    cudaGetSymbolAddress((void**)&w1r, g_w1r);
    cudaGetSymbolAddress((void**)&w2r, g_w2r);

    static bool attr_done = false;
    if (!attr_done) {
        cudaFuncSetAttribute(mma_gemm_kernel<true,  F_>,
                             cudaFuncAttributeMaxDynamicSharedMemorySize, SMEM_BYTES);
        cudaFuncSetAttribute(mma_gemm_kernel<false, D_>,
                             cudaFuncAttributeMaxDynamicSharedMemorySize, SMEM_BYTES);
        attr_done = true;
    }

    // pre-pass: round inputs to tf32 (rna) once
    const int nx  = E_ * T_ * D_ / 4;
    const int nw1 = E_ * D_ * F_ / 4;
    const int nw2 = E_ * D_ * D_ / 4;
    round_tf32_kernel<<<4096, 256>>>((const float4*)x,  (float4*)xr,  nx);
    round_tf32_kernel<<<4096, 256>>>((const float4*)w1, (float4*)w1r, nw1);
    round_tf32_kernel<<<4096, 256>>>((const float4*)w2, (float4*)w2r, nw2);

    // GEMM1 + bias + SwiGLU -> act (pre-rounded)   (M=2048, N=4096, K=2048)
    dim3 g1(F_ / BN, T_ / BM, E_);
    mma_gemm_kernel<true,  F_><<<g1, 256, SMEM_BYTES>>>(xr, w1r, b1, act);

    // GEMM2 + bias -> out                          (M=2048, N=2048, K=2048)
    dim3 g2(D_ / BN, T_ / BM, E_);
    mma_gemm_kernel<false, D_><<<g2, 256, SMEM_BYTES>>>(act, w2r, b2, out);
}

// round 8
// speedup vs baseline: 8.1616x; 1.9197x over previous
#include <cuda_runtime.h>
#include <cuda_fp16.h>
#include <cstdint>

// ============================================================================
// GroupedExperts: out = swiglu(x@W1+b1) @ W2 + b2   (E=8, T=2048, D=2048)
// R8: fp16 (same 11-bit mantissa as tf32) mma.sync m16n8k16, fp32 accumulate.
// 2x tensor throughput + half the SMEM traffic vs R7's tf32. Pre-pass converts
// x/W1/W2 to fp16; GEMM1 epilogue stores act as fp16. B frags via ldmatrix.trans.
// ============================================================================

namespace {
constexpr int E_ = 8;
constexpr int T_ = 2048;
constexpr int D_ = 2048;
constexpr int F_ = 4096;

constexpr int BM = 128, BN = 128, BK = 64;
constexpr int STAGES = 3;
constexpr int NT = D_ / BK;                   // 32 k-tiles (K=2048 both GEMMs)

constexpr int BPITCH = 272;                   // B row pitch bytes (17*16 -> conflict-free)
constexpr int A_STAGE_B = BM * BK * 2;        // 16384 B (128 rows x 128B)
constexpr int B_STAGE_B = BK * BPITCH;        // 17408 B
constexpr int STAGE_B   = A_STAGE_B + B_STAGE_B;    // 33792
constexpr int SMEM_BYTES = STAGES * STAGE_B + 128;  // ~99.1 KB -> 2 CTAs/SM

constexpr float ALPHA_ = 1.702f;
constexpr float LIMIT_ = 7.0f;
}

// scratch (no allocations allowed): fp16 copies + fp16 activation
__device__ __half g_acth[(size_t)E_ * T_ * D_];   // 64 MiB
__device__ __half g_xh  [(size_t)E_ * T_ * D_];   // 64 MiB
__device__ __half g_w1h [(size_t)E_ * D_ * F_];   // 128 MiB
__device__ __half g_w2h [(size_t)E_ * D_ * D_];   // 64 MiB

// ---------------- PTX helpers ----------------
__device__ __forceinline__ uint32_t smem_u32(const void* p) {
    uint32_t a;
    asm("{ .reg .u64 t; cvta.to.shared.u64 t, %1; cvt.u32.u64 %0, t; }" : "=r"(a) : "l"(p));
    return a;
}
__device__ __forceinline__ uint32_t swzA(uint32_t row, uint32_t ch) {
    // 128B rows, 16B chunks, chunk ^= row&7
    return row * 128u + ((ch ^ (row & 7u)) * 16u);
}
__device__ __forceinline__ void cpasync16(uint32_t dst, const void* src) {
    asm volatile("cp.async.cg.shared.global [%0], [%1], 16;" :: "r"(dst), "l"(src) : "memory");
}
__device__ __forceinline__ void cp_commit() {
    asm volatile("cp.async.commit_group;" ::: "memory");
}
template <int N>
__device__ __forceinline__ void cp_wait() {
    asm volatile("cp.async.wait_group %0;" :: "n"(N) : "memory");
}
__device__ __forceinline__ void ldsm_x4(uint32_t* r, uint32_t addr) {
    asm volatile("ldmatrix.sync.aligned.m8n8.x4.shared.b16 {%0,%1,%2,%3}, [%4];"
                 : "=r"(r[0]), "=r"(r[1]), "=r"(r[2]), "=r"(r[3]) : "r"(addr));
}
__device__ __forceinline__ void ldsm_x4_t(uint32_t* r, uint32_t addr) {
    asm volatile("ldmatrix.sync.aligned.m8n8.x4.trans.shared.b16 {%0,%1,%2,%3}, [%4];"
                 : "=r"(r[0]), "=r"(r[1]), "=r"(r[2]), "=r"(r[3]) : "r"(addr));
}
__device__ __forceinline__ void mma_f16(float* c, const uint32_t* a, const uint32_t* b) {
    asm volatile(
        "mma.sync.aligned.m16n8k16.row.col.f32.f16.f16.f32 "
        "{%0,%1,%2,%3}, {%4,%5,%6,%7}, {%8,%9}, {%0,%1,%2,%3};"
        : "+f"(c[0]), "+f"(c[1]), "+f"(c[2]), "+f"(c[3])
        : "r"(a[0]), "r"(a[1]), "r"(a[2]), "r"(a[3]), "r"(b[0]), "r"(b[1]));
}

// ---------------- pre-pass: fp32 -> fp16(rn) ----------------
__global__ void to_half_kernel(const float4* __restrict__ src,
                               uint2* __restrict__ dst, int n4)
{
    int i = blockIdx.x * blockDim.x + threadIdx.x;
    const int stride = gridDim.x * blockDim.x;
    for (; i < n4; i += stride) {
        float4 v = src[i];
        __half2 h0 = __floats2half2_rn(v.x, v.y);
        __half2 h1 = __floats2half2_rn(v.z, v.w);
        uint2 u;
        u.x = *reinterpret_cast<uint32_t*>(&h0);
        u.y = *reinterpret_cast<uint32_t*>(&h1);
        dst[i] = u;
    }
}

// ----------------------------------------------------------------------------
// C 128x128 tile = A[128, K] @ W[K, NTOT slice 128]  (+bias, optional SwiGLU)
// A: fp16 row-major (K contiguous). W: fp16 row-major (N contiguous).
// ----------------------------------------------------------------------------
template <bool FUSE, int NTOT, typename OutT>
__global__ __launch_bounds__(256, 2)
void hmma_gemm_kernel(const __half* __restrict__ Ag,
                      const __half* __restrict__ Wg,
                      const float* __restrict__ biasg,
                      OutT* __restrict__ Cg)
{
    extern __shared__ float dsm[];
    const int tid  = threadIdx.x;
    const int wid  = tid >> 5;
    const int lane = tid & 31;
    const int e  = blockIdx.z;
    const int bm = blockIdx.y * BM;
    const int bn = blockIdx.x * BN;

    const __half* Ae = Ag + ((size_t)e * T_ + bm) * D_;
    const __half* We = Wg + (size_t)e * D_ * NTOT + bn;
    const float*  Be = biasg + (size_t)e * NTOT + bn;

    const uint32_t s0 = (smem_u32(dsm) + 127u) & ~127u;
    const uint32_t sEnd = s0 + STAGES * STAGE_B;

    // --- producer state: A = 1024 chunks (4/thr), B = 1024 chunks (4/thr) ---
    const int pArow = tid >> 3, pAc = tid & 7;            // A: 128 rows x 8 chunks
    const uint32_t pAoff = swzA(pArow, pAc);
    const uint32_t pAg   = (uint32_t)pArow * D_ + pAc * 8;
    const int pBk = tid >> 4, pBc = tid & 15;             // B: 64 rows x 16 chunks
    const uint32_t pBoff = (uint32_t)pBk * BPITCH + pBc * 16;
    const uint32_t pBg   = (uint32_t)pBk * NTOT + pBc * 8;

    const __half* aSrc = Ae;
    const __half* bSrc = We;
    uint32_t prodBase = s0;
    auto produce = [&]() {
        #pragma unroll
        for (int i = 0; i < 4; i++)
            cpasync16(prodBase + pAoff + i * (32u * 128u),
                      aSrc + pAg + (size_t)(32 * i) * D_);
        const uint32_t pb = prodBase + A_STAGE_B;
        #pragma unroll
        for (int i = 0; i < 4; i++)
            cpasync16(pb + pBoff + i * (16u * BPITCH),
                      bSrc + pBg + (size_t)(16 * i) * NTOT);
        cp_commit();
        aSrc += BK;
        bSrc += (size_t)BK * NTOT;
        prodBase += STAGE_B;
        if (prodBase == sEnd) prodBase = s0;
    };

    produce();
    produce();

    const int wm = (wid >> 2) * 64;   // warp m offset (0/64)
    const int wn = (wid & 3) * 32;    // warp n offset (0/32/64/96)

    float acc[4][4][4];
    #pragma unroll
    for (int mi = 0; mi < 4; mi++)
        #pragma unroll
        for (int ni = 0; ni < 4; ni++)
            #pragma unroll
            for (int v = 0; v < 4; v++) acc[mi][ni][v] = 0.0f;

    // --- consumer constants ---
    const int lrow = lane & 15;                 // A ldsm: rows, k-chunk via lane>>4
    const int lchx = lane >> 4;
    const uint32_t rx = (uint32_t)(lrow & 7);
    uint32_t aRowOff[4];
    #pragma unroll
    for (int mi = 0; mi < 4; mi++)
        aRowOff[mi] = (uint32_t)(wm + mi * 16 + lrow) * 128u;
    // B ldsm.trans: lanes 0-7: klo rows nc0 | 8-15: khi nc0 | 16-23: klo nc1 | 24-31: khi nc1
    const uint32_t bLaneOff = (uint32_t)(lane & 15) * BPITCH
                            + (uint32_t)((wn >> 3) + (lane >> 4)) * 16u;

    uint32_t consBase = s0;
    for (int kt = 0; kt < NT; kt++) {
        cp_wait<STAGES - 2>();
        __syncthreads();
        if (kt + STAGES - 1 < NT) produce();

        const uint32_t sA = consBase;
        const uint32_t sBl = consBase + A_STAGE_B + bLaneOff;

        uint32_t b[2][4][2];
        {   // B frags for ks=0: two x4.trans cover ni 0..3
            uint32_t r[4];
            ldsm_x4_t(r, sBl);
            b[0][0][0]=r[0]; b[0][0][1]=r[1]; b[0][1][0]=r[2]; b[0][1][1]=r[3];
            ldsm_x4_t(r, sBl + 32u);
            b[0][2][0]=r[0]; b[0][2][1]=r[1]; b[0][3][0]=r[2]; b[0][3][1]=r[3];
        }

        #pragma unroll
        for (int ks = 0; ks < 4; ks++) {        // k16 steps within BK=64
            uint32_t a[4][4];
            #pragma unroll
            for (int mi = 0; mi < 4; mi++) {
                uint32_t ch = ((uint32_t)(2 * ks + lchx) ^ rx) * 16u;
                ldsm_x4(a[mi], sA + aRowOff[mi] + ch);
            }
            if (ks < 3) {                       // prefetch B(ks+1)
                const uint32_t nb = sBl + (uint32_t)(ks + 1) * (16u * BPITCH);
                uint32_t r[4];
                ldsm_x4_t(r, nb);
                b[(ks+1)&1][0][0]=r[0]; b[(ks+1)&1][0][1]=r[1];
                b[(ks+1)&1][1][0]=r[2]; b[(ks+1)&1][1][1]=r[3];
                ldsm_x4_t(r, nb + 32u);
                b[(ks+1)&1][2][0]=r[0]; b[(ks+1)&1][2][1]=r[1];
                b[(ks+1)&1][3][0]=r[2]; b[(ks+1)&1][3][1]=r[3];
            }
            #pragma unroll
            for (int mi = 0; mi < 4; mi++)
                #pragma unroll
                for (int ni = 0; ni < 4; ni++)
                    mma_f16(acc[mi][ni], a[mi], b[ks & 1][ni]);
        }

        consBase += STAGE_B;
        if (consBase == sEnd) consBase = s0;
    }

    // ------------------------------ epilogue ------------------------------
    #pragma unroll
    for (int ni = 0; ni < 4; ni++) {
        const int cl = wn + ni * 8 + 2 * (lane & 3);     // even col within tile
        const float b_e = Be[cl];
        const float b_o = Be[cl + 1];
        #pragma unroll
        for (int mi = 0; mi < 4; mi++) {
            const int r0 = bm + wm + mi * 16 + (lane >> 2);
            #pragma unroll
            for (int h = 0; h < 2; h++) {
                const float v0 = acc[mi][ni][2 * h + 0] + b_e;
                const float v1 = acc[mi][ni][2 * h + 1] + b_o;
                const size_t row = (size_t)e * T_ + r0 + 8 * h;
                if (FUSE) {
                    float g = fminf(v0, LIMIT_);
                    float l = fminf(fmaxf(v1, -LIMIT_), LIMIT_);
                    float sg = 1.0f / (1.0f + __expf(-ALPHA_ * g));
                    ((__half*)Cg)[row * D_ + ((bn + cl) >> 1)] =
                        __float2half_rn(g * sg * (l + 1.0f));
                } else {
                    float2 o = make_float2(v0, v1);
                    *(float2*)((float*)Cg + row * D_ + bn + cl) = o;
                }
            }
        }
    }
}

// ----------------------------------------------------------------------------
extern "C" void kernel_launch(void* const* d_in, const int* in_sizes, int n_in,
                              void* d_out, int out_size)
{
    (void)in_sizes; (void)n_in; (void)out_size;
    const float* x  = (const float*)d_in[0];
    const float* w1 = (const float*)d_in[1];
    const float* b1 = (const float*)d_in[2];
    const float* w2 = (const float*)d_in[3];
    const float* b2 = (const float*)d_in[4];
    float* out = (float*)d_out;

    __half *acth, *xh, *w1h, *w2h;
    cudaGetSymbolAddress((void**)&acth, g_acth);
    cudaGetSymbolAddress((void**)&xh,   g_xh);
    cudaGetSymbolAddress((void**)&w1h,  g_w1h);
    cudaGetSymbolAddress((void**)&w2h,  g_w2h);

    static bool attr_done = false;
    if (!attr_done) {
        cudaFuncSetAttribute(hmma_gemm_kernel<true,  F_, __half>,
                             cudaFuncAttributeMaxDynamicSharedMemorySize, SMEM_BYTES);
        cudaFuncSetAttribute(hmma_gemm_kernel<false, D_, float>,
                             cudaFuncAttributeMaxDynamicSharedMemorySize, SMEM_BYTES);
        attr_done = true;
    }

    // pre-pass: fp32 -> fp16 once
    const int nx  = E_ * T_ * D_ / 4;
    const int nw1 = E_ * D_ * F_ / 4;
    const int nw2 = E_ * D_ * D_ / 4;
    to_half_kernel<<<4096, 256>>>((const float4*)x,  (uint2*)xh,  nx);
    to_half_kernel<<<4096, 256>>>((const float4*)w1, (uint2*)w1h, nw1);
    to_half_kernel<<<4096, 256>>>((const float4*)w2, (uint2*)w2h, nw2);

    // GEMM1 + bias + SwiGLU -> act (fp16)   (M=2048, N=4096, K=2048)
    dim3 g1(F_ / BN, T_ / BM, E_);
    hmma_gemm_kernel<true,  F_, __half><<<g1, 256, SMEM_BYTES>>>(xh, w1h, b1, acth);

    // GEMM2 + bias -> out (fp32)            (M=2048, N=2048, K=2048)
    dim3 g2(D_ / BN, T_ / BM, E_);
    hmma_gemm_kernel<false, D_, float><<<g2, 256, SMEM_BYTES>>>(acth, w2h, b2, out);
}